// round 12
// baseline (speedup 1.0000x reference)
#include <cuda_runtime.h>
#include <cuda_bf16.h>
#include <cuda_fp16.h>
#include <math.h>

#define N_NODES 100000
#define N_EDGES 1600000
#define HIDC    128
#define SCAN_NB 98

typedef unsigned int u32;
typedef unsigned long long u64;
typedef unsigned short u16;

// ---------------- device scratch (static globals; no allocation) ----------------
__device__ u32   d_aggb2[(size_t)N_NODES * HIDC];   // aggregated mean, bf16 pairs
__device__ u32   d_h1b2 [(size_t)N_NODES * HIDC];   // layer1 out bf16 pairs (gemm2 A)
__device__ u32   d_h2b2 [(size_t)N_NODES * HIDC];   // layer2 out bf16 pairs (gemm80 A)
__device__ u32   d_xh   [(size_t)N_NODES * 64];     // x   as fp16 (2/word)  - agg gather
__device__ u32   d_h1h  [(size_t)N_NODES * 64];     // h1  as fp16 (2/word)  - agg gather
__device__ float d_zs   [(size_t)N_NODES * 40];     // layer3 self+bias fp32
__device__ u32   d_z40h [(size_t)N_NODES * 20];     // layer3 neigh logits fp16
__device__ int   d_counts[N_NODES + 1];
__device__ int   d_rowptr[N_NODES + 1];
__device__ int   d_cursor[N_NODES];
__device__ int   d_csr[N_EDGES];
__device__ int   d_blocksum[SCAN_NB];
__device__ float d_scale1[HIDC], d_shift1[HIDC], d_scale2[HIDC], d_shift2[HIDC];
// layer-1/2 weight images: [layer*2+mat][split][n(128)][k(128)] bf16
__device__ __align__(16) u16 d_wimg[4 * 2 * 128 * 128];
// layer-3 weight image: [split(2)][ck(4)][n(96)][jj(32)]; n<40 Ws3, 40..79 Wn3, else 0
__device__ __align__(16) u16 d_wimg3[2 * 4 * 96 * 32];

// ---------------- helpers ----------------
__device__ __forceinline__ u32 smem_u32(const void* p) {
    u32 a;
    asm("{ .reg .u64 t; cvta.to.shared.u64 t, %1; cvt.u32.u64 %0, t; }" : "=r"(a) : "l"(p));
    return a;
}
// pack fp32 -> (lo_bf16<<16)|hi_bf16, truncation split
__device__ __forceinline__ u32 packb2(float f) {
    u32 t = __float_as_uint(f);
    float r = f - __uint_as_float(t & 0xFFFF0000u);
    return __byte_perm(t, __float_as_uint(r), 0x7632);
}
__device__ __forceinline__ void split16(float f, u16& h, u16& l) {
    u32 t = __float_as_uint(f);
    h = (u16)(t >> 16);
    float r = f - __uint_as_float(t & 0xFFFF0000u);
    l = (u16)(__float_as_uint(r) >> 16);
}
__device__ __forceinline__ u32 h2u(__half2 h) { return *reinterpret_cast<u32*>(&h); }
__device__ __forceinline__ float2 u2f(u32 v) {
    __half2 h = *reinterpret_cast<__half2*>(&v);
    return __half22float2(h);
}
__device__ __forceinline__ void ldmx4(u32& r0, u32& r1, u32& r2, u32& r3, u32 addr) {
    asm volatile("ldmatrix.sync.aligned.m8n8.x4.shared.b16 {%0,%1,%2,%3}, [%4];"
                 : "=r"(r0), "=r"(r1), "=r"(r2), "=r"(r3) : "r"(addr));
}
__device__ __forceinline__ void mma16816(float* d, const u32* a, u32 b0, u32 b1) {
    asm volatile("mma.sync.aligned.m16n8k16.row.col.f32.bf16.bf16.f32 "
                 "{%0,%1,%2,%3}, {%4,%5,%6,%7}, {%8,%9}, {%0,%1,%2,%3};"
                 : "+f"(d[0]), "+f"(d[1]), "+f"(d[2]), "+f"(d[3])
                 : "r"(a[0]), "r"(a[1]), "r"(a[2]), "r"(a[3]), "r"(b0), "r"(b1));
}

// ---------------- small prep kernels ----------------
__global__ void prep_bn(const float* b1, const float* g1, const float* be1,
                        const float* m1, const float* v1,
                        const float* b2, const float* g2, const float* be2,
                        const float* m2, const float* v2) {
    int c = threadIdx.x;
    if (c < HIDC) {
        float s1 = g1[c] * rsqrtf(v1[c] + 1e-5f);
        d_scale1[c] = s1; d_shift1[c] = (b1[c] - m1[c]) * s1 + be1[c];
        float s2 = g2[c] * rsqrtf(v2[c] + 1e-5f);
        d_scale2[c] = s2; d_shift2[c] = (b2[c] - m2[c]) * s2 + be2[c];
    }
}

// layer-1/2 weights -> hi/lo split images, transposed to [n][k]
__global__ void prep_w(const float* __restrict__ Ws1, const float* __restrict__ Wn1,
                       const float* __restrict__ Ws2, const float* __restrict__ Wn2) {
    int idx = blockIdx.x * 256 + threadIdx.x;       // 0 .. 4*16384-1
    if (idx >= 4 * 16384) return;
    int mat4 = idx >> 14;
    int e = idx & 16383;
    int k = e >> 7, n = e & 127;
    const float* W = (mat4 == 0) ? Ws1 : (mat4 == 1) ? Wn1 : (mat4 == 2) ? Ws2 : Wn2;
    u16 h, l; split16(W[k * 128 + n], h, l);
    d_wimg[((size_t)(mat4 * 2 + 0) * 128 + n) * 128 + k] = h;
    d_wimg[((size_t)(mat4 * 2 + 1) * 128 + n) * 128 + k] = l;
}

// layer-3 weights -> split image [split][ck][n96][jj32]
__global__ void prep_w3(const float* __restrict__ Ws3, const float* __restrict__ Wn3) {
    int idx = blockIdx.x * 256 + threadIdx.x;       // 0 .. 24575
    if (idx >= 2 * 4 * 96 * 32) return;
    int jj = idx & 31;
    int t2 = idx >> 5;
    int n = t2 % 96;
    int t3 = t2 / 96;
    int ck = t3 & 3;
    int split = t3 >> 2;
    int k = ck * 32 + jj;
    float w = 0.f;
    if (n < 40)      w = Ws3[k * 40 + n];
    else if (n < 80) w = Wn3[k * 40 + (n - 40)];
    u16 h, l; split16(w, h, l);
    d_wimg3[idx] = split ? l : h;
}

// x -> fp16 only (aggregation gather); gemm1 reads fp32 x directly
__global__ void conv_xh(const float* __restrict__ x) {
    int i = blockIdx.x * 256 + threadIdx.x;
    if (i < N_NODES * 32) {
        float4 v = ((const float4*)x)[i];
        uint2 hh;
        hh.x = h2u(__floats2half2_rn(v.x, v.y));
        hh.y = h2u(__floats2half2_rn(v.z, v.w));
        ((uint2*)d_xh)[i] = hh;
    }
}

// ---------------- CSR build ----------------
__global__ void zero_counts() {
    int i = blockIdx.x * blockDim.x + threadIdx.x;
    if (i < N_NODES) d_counts[i] = 0;
}
__global__ void hist_kernel(const int* __restrict__ dst) {
    int e = blockIdx.x * blockDim.x + threadIdx.x;
    if (e < N_EDGES) atomicAdd(&d_counts[dst[e]], 1);
}
__global__ void scanA() {
    __shared__ int sh[1024];
    int i = blockIdx.x * 1024 + threadIdx.x;
    sh[threadIdx.x] = (i < N_NODES) ? d_counts[i] : 0;
    __syncthreads();
    for (int s = 512; s > 0; s >>= 1) {
        if (threadIdx.x < s) sh[threadIdx.x] += sh[threadIdx.x + s];
        __syncthreads();
    }
    if (threadIdx.x == 0) d_blocksum[blockIdx.x] = sh[0];
}
__global__ void scanB() {
    if (threadIdx.x == 0) {
        int acc = 0;
        for (int b = 0; b < SCAN_NB; b++) { int t = d_blocksum[b]; d_blocksum[b] = acc; acc += t; }
    }
}
__global__ void scanC() {   // also seeds d_cursor
    __shared__ int sh[2][1024];
    int t = threadIdx.x;
    int i = blockIdx.x * 1024 + t;
    int v = (i < N_NODES) ? d_counts[i] : 0;
    sh[0][t] = v;
    __syncthreads();
    int cur = 0;
    for (int off = 1; off < 1024; off <<= 1) {
        int val = sh[cur][t];
        if (t >= off) val += sh[cur][t - off];
        sh[cur ^ 1][t] = val;
        cur ^= 1;
        __syncthreads();
    }
    int excl = sh[cur][t] - v + d_blocksum[blockIdx.x];
    if (i <= N_NODES) d_rowptr[i] = excl;
    if (i < N_NODES)  d_cursor[i] = excl;
}
__global__ void fill_csr(const int* __restrict__ src, const int* __restrict__ dst) {
    int e = blockIdx.x * blockDim.x + threadIdx.x;
    if (e < N_EDGES) {
        int d = dst[e];
        int p = atomicAdd(&d_cursor[d], 1);
        d_csr[p] = src[e];
    }
}

// ---------------- aggregation (warp per node, F=128), fp16 gather, MLP=4 ------
// SRC==0: d_xh.  SRC==1: d_h1h.  fp32 accumulate -> bf16-pair means out.
template<int SRC>
__global__ void agg128() {
    int w = (blockIdx.x * blockDim.x + threadIdx.x) >> 5;
    if (w >= N_NODES) return;
    const u32* __restrict__ xh = (SRC == 0) ? (const u32*)d_xh : (const u32*)d_h1h;
    int lane = threadIdx.x & 31;
    int s = d_rowptr[w], e = d_rowptr[w + 1];
    float4 a0 = make_float4(0.f, 0.f, 0.f, 0.f);
    float4 a1 = make_float4(0.f, 0.f, 0.f, 0.f);
    float4 a2 = make_float4(0.f, 0.f, 0.f, 0.f);
    float4 a3 = make_float4(0.f, 0.f, 0.f, 0.f);
    int i = s;
    for (; i + 3 < e; i += 4) {
        int s0 = d_csr[i], s1 = d_csr[i + 1], s2 = d_csr[i + 2], s3 = d_csr[i + 3];
        uint2 v0 = __ldg((const uint2*)(xh + (size_t)s0 * 64) + lane);
        uint2 v1 = __ldg((const uint2*)(xh + (size_t)s1 * 64) + lane);
        uint2 v2 = __ldg((const uint2*)(xh + (size_t)s2 * 64) + lane);
        uint2 v3 = __ldg((const uint2*)(xh + (size_t)s3 * 64) + lane);
        float2 f;
        f = u2f(v0.x); a0.x += f.x; a0.y += f.y;
        f = u2f(v0.y); a0.z += f.x; a0.w += f.y;
        f = u2f(v1.x); a1.x += f.x; a1.y += f.y;
        f = u2f(v1.y); a1.z += f.x; a1.w += f.y;
        f = u2f(v2.x); a2.x += f.x; a2.y += f.y;
        f = u2f(v2.y); a2.z += f.x; a2.w += f.y;
        f = u2f(v3.x); a3.x += f.x; a3.y += f.y;
        f = u2f(v3.y); a3.z += f.x; a3.w += f.y;
    }
    for (; i < e; i++) {
        int s0 = d_csr[i];
        uint2 v0 = __ldg((const uint2*)(xh + (size_t)s0 * 64) + lane);
        float2 f;
        f = u2f(v0.x); a0.x += f.x; a0.y += f.y;
        f = u2f(v0.y); a0.z += f.x; a0.w += f.y;
    }
    a0.x += a1.x; a0.y += a1.y; a0.z += a1.z; a0.w += a1.w;
    a2.x += a3.x; a2.y += a3.y; a2.z += a3.z; a2.w += a3.w;
    a0.x += a2.x; a0.y += a2.y; a0.z += a2.z; a0.w += a2.w;
    float inv = (e > s) ? 1.0f / (float)(e - s) : 0.0f;
    uint4 o;
    o.x = packb2(a0.x * inv); o.y = packb2(a0.y * inv);
    o.z = packb2(a0.z * inv); o.w = packb2(a0.w * inv);
    *((uint4*)(d_aggb2 + (size_t)w * HIDC) + lane) = o;
}

// ---------------- mma.sync fused two-input GEMM (layers 1 & 2) ----------------
// D = Aself@W1 + Aneigh@W2 via bf16 hi/lo 3-split, fp32 register accumulators.
// LAYER 1: Aself = fp32 x (split on the fly).  LAYER 2: Aself = d_h1b2 pairs.
#define APITCH 40   // bf16 pitch; 80B = 5 x 16B (odd mod 8 -> ldmatrix conflict-free)

template<int LAYER>
__global__ __launch_bounds__(256, 2) void gemm_mma(const float* __restrict__ xf) {
    __shared__ __align__(16) u16 sAhi[128 * APITCH];
    __shared__ __align__(16) u16 sAlo[128 * APITCH];
    __shared__ __align__(16) u16 sBhi[128 * APITCH];
    __shared__ __align__(16) u16 sBlo[128 * APITCH];
    __shared__ float s_sc[128], s_sh[128];

    int tid = threadIdx.x, lane = tid & 31, wid = tid >> 5;
    int wm = wid >> 1, wn = wid & 1;
    int rbase = blockIdx.x * 128;

    if (tid < 128) {
        s_sc[tid] = (LAYER == 1) ? d_scale1[tid] : d_scale2[tid];
        s_sh[tid] = (LAYER == 1) ? d_shift1[tid] : d_shift2[tid];
    }

    const u16* __restrict__ wL = d_wimg + (size_t)(LAYER - 1) * 2 * 2 * 16384;

    float acc[2][8][4];
#pragma unroll
    for (int mt = 0; mt < 2; mt++)
#pragma unroll
        for (int nt = 0; nt < 8; nt++)
#pragma unroll
            for (int r = 0; r < 4; r++) acc[mt][nt][r] = 0.f;

    int laneRow = (lane & 7) + ((lane >> 3) & 1) * 8;
    int laneK8  = (lane >> 4) * 8;
    u32 baseAhi = smem_u32(sAhi), baseAlo = smem_u32(sAlo);
    u32 baseBhi = smem_u32(sBhi), baseBlo = smem_u32(sBlo);

    for (int phase = 0; phase < 2; ++phase) {
        const u16* __restrict__ wimg = wL + (size_t)phase * 2 * 16384;
        for (int ck = 0; ck < 4; ++ck) {
            __syncthreads();
            // ---- A chunk (128 rows x 32 k) ----
#pragma unroll
            for (int i = 0; i < 4; i++) {
                int idx = tid + i * 256;
                int row = idx >> 3, q = idx & 7;
                int grow = rbase + row; if (grow >= N_NODES) grow = N_NODES - 1;
                u32* dh = (u32*)sAhi + row * (APITCH / 2) + q * 2;
                u32* dl = (u32*)sAlo + row * (APITCH / 2) + q * 2;
                if (LAYER == 1 && phase == 0) {
                    // fp32 x: split on the fly
                    float4 v = *(const float4*)(xf + (size_t)grow * HIDC + ck * 32 + q * 4);
                    u32 t0 = __float_as_uint(v.x), t1 = __float_as_uint(v.y);
                    u32 t2 = __float_as_uint(v.z), t3 = __float_as_uint(v.w);
                    float r0 = v.x - __uint_as_float(t0 & 0xFFFF0000u);
                    float r1 = v.y - __uint_as_float(t1 & 0xFFFF0000u);
                    float r2 = v.z - __uint_as_float(t2 & 0xFFFF0000u);
                    float r3 = v.w - __uint_as_float(t3 & 0xFFFF0000u);
                    dh[0] = __byte_perm(t0, t1, 0x7632);
                    dh[1] = __byte_perm(t2, t3, 0x7632);
                    dl[0] = __byte_perm(__float_as_uint(r0), __float_as_uint(r1), 0x7632);
                    dl[1] = __byte_perm(__float_as_uint(r2), __float_as_uint(r3), 0x7632);
                } else {
                    const u32* Apair = phase ? (const u32*)d_aggb2 : (const u32*)d_h1b2;
                    uint4 v = *(const uint4*)(Apair + (size_t)grow * HIDC + ck * 32 + q * 4);
                    dh[0] = __byte_perm(v.x, v.y, 0x5410);
                    dh[1] = __byte_perm(v.z, v.w, 0x5410);
                    dl[0] = __byte_perm(v.x, v.y, 0x7632);
                    dl[1] = __byte_perm(v.z, v.w, 0x7632);
                }
            }
#pragma unroll
            for (int i = 0; i < 4; i++) {
                int idx = tid + i * 256;
                int split = idx >> 9, r = idx & 511;
                int row = r >> 2, q = r & 3;
                uint4 v = *((const uint4*)(wimg + ((size_t)split * 128 + row) * 128 + ck * 32) + q);
                u16* dstb = split ? sBlo : sBhi;
                uint2* d2 = (uint2*)(dstb + row * APITCH + q * 8);
                d2[0] = make_uint2(v.x, v.y);
                d2[1] = make_uint2(v.z, v.w);
            }
            __syncthreads();
#pragma unroll
            for (int round = 0; round < 3; ++round) {
                u32 baseA = (round == 2) ? baseAlo : baseAhi;
                u32 baseB = (round == 1) ? baseBlo : baseBhi;
#pragma unroll
                for (int ks = 0; ks < 2; ++ks) {
                    u32 a[2][4];
#pragma unroll
                    for (int mt = 0; mt < 2; mt++) {
                        int arow = wm * 32 + mt * 16 + laneRow;
                        u32 addr = baseA + (u32)((arow * APITCH + ks * 16 + laneK8) * 2);
                        ldmx4(a[mt][0], a[mt][1], a[mt][2], a[mt][3], addr);
                    }
#pragma unroll
                    for (int t = 0; t < 4; t++) {
                        int brow = wn * 64 + t * 16 + laneRow;
                        u32 addr = baseB + (u32)((brow * APITCH + ks * 16 + laneK8) * 2);
                        u32 b0, b1, b2, b3;
                        ldmx4(b0, b1, b2, b3, addr);
                        mma16816(acc[0][2 * t],     a[0], b0, b2);
                        mma16816(acc[0][2 * t + 1], a[0], b1, b3);
                        mma16816(acc[1][2 * t],     a[1], b0, b2);
                        mma16816(acc[1][2 * t + 1], a[1], b1, b3);
                    }
                }
            }
        }
    }

    // ---------------- epilogue: BN + ReLU -> bf16 pairs (+ fp16 for LAYER 1) ---
    u32* __restrict__ OUTP = (LAYER == 1) ? d_h1b2 : d_h2b2;
#pragma unroll
    for (int mt = 0; mt < 2; mt++) {
#pragma unroll
        for (int nt = 0; nt < 8; nt++) {
            int col = wn * 64 + nt * 8 + (lane & 3) * 2;
            float sc0 = s_sc[col], sc1 = s_sc[col + 1];
            float sh0 = s_sh[col], sh1 = s_sh[col + 1];
            int row = rbase + wm * 32 + mt * 16 + (lane >> 2);
            float v0 = fmaxf(fmaf(acc[mt][nt][0], sc0, sh0), 0.f);
            float v1 = fmaxf(fmaf(acc[mt][nt][1], sc1, sh1), 0.f);
            float v2 = fmaxf(fmaf(acc[mt][nt][2], sc0, sh0), 0.f);
            float v3 = fmaxf(fmaf(acc[mt][nt][3], sc1, sh1), 0.f);
            if (row < N_NODES) {
                *(uint2*)(OUTP + (size_t)row * HIDC + col) =
                    make_uint2(packb2(v0), packb2(v1));
                if (LAYER == 1)
                    d_h1h[(size_t)row * 64 + (col >> 1)] = h2u(__floats2half2_rn(v0, v1));
            }
            if (row + 8 < N_NODES) {
                *(uint2*)(OUTP + (size_t)(row + 8) * HIDC + col) =
                    make_uint2(packb2(v2), packb2(v3));
                if (LAYER == 1)
                    d_h1h[(size_t)(row + 8) * 64 + (col >> 1)] = h2u(__floats2half2_rn(v2, v3));
            }
        }
    }
}

// ---------------- layer-3 GEMM (mma.sync, 3-split) ----------------------------
// CTA tile 128 x 96 (cols 80..95 zero-pad), 8 warps 4(m)x2(n), 48 cols/warp.
// Epilogue: self cols -> d_zs fp32 (+bias); neigh cols -> d_z40h fp16.
__global__ __launch_bounds__(256, 2) void gemm80_mma(const float* __restrict__ b3) {
    __shared__ __align__(16) u16 sAhi[128 * APITCH];
    __shared__ __align__(16) u16 sAlo[128 * APITCH];
    __shared__ __align__(16) u16 sBhi[96 * APITCH];
    __shared__ __align__(16) u16 sBlo[96 * APITCH];
    __shared__ float s_b3[40];

    int tid = threadIdx.x, lane = tid & 31, wid = tid >> 5;
    int wm = wid >> 1, wn = wid & 1;
    int rbase = blockIdx.x * 128;

    if (tid < 40) s_b3[tid] = b3[tid];

    float acc[2][6][4];
#pragma unroll
    for (int mt = 0; mt < 2; mt++)
#pragma unroll
        for (int nt = 0; nt < 6; nt++)
#pragma unroll
            for (int r = 0; r < 4; r++) acc[mt][nt][r] = 0.f;

    int laneRow = (lane & 7) + ((lane >> 3) & 1) * 8;
    int laneK8  = (lane >> 4) * 8;
    u32 baseAhi = smem_u32(sAhi), baseAlo = smem_u32(sAlo);
    u32 baseBhi = smem_u32(sBhi), baseBlo = smem_u32(sBlo);

    for (int ck = 0; ck < 4; ++ck) {
        __syncthreads();
#pragma unroll
        for (int i = 0; i < 4; i++) {
            int idx = tid + i * 256;
            int row = idx >> 3, q = idx & 7;
            int grow = rbase + row; if (grow >= N_NODES) grow = N_NODES - 1;
            uint4 v = *(const uint4*)((const u32*)d_h2b2 + (size_t)grow * HIDC + ck * 32 + q * 4);
            u32* dh = (u32*)sAhi + row * (APITCH / 2) + q * 2;
            u32* dl = (u32*)sAlo + row * (APITCH / 2) + q * 2;
            dh[0] = __byte_perm(v.x, v.y, 0x5410);
            dh[1] = __byte_perm(v.z, v.w, 0x5410);
            dl[0] = __byte_perm(v.x, v.y, 0x7632);
            dl[1] = __byte_perm(v.z, v.w, 0x7632);
        }
#pragma unroll
        for (int i = 0; i < 3; i++) {
            int idx = tid + i * 256;        // 0..767
            int split = idx / 384, r = idx % 384;
            int row = r >> 2, q = r & 3;
            uint4 v = *((const uint4*)(d_wimg3 + ((size_t)(split * 4 + ck) * 96 + row) * 32) + q);
            u16* dstb = split ? sBlo : sBhi;
            uint2* d2 = (uint2*)(dstb + row * APITCH + q * 8);
            d2[0] = make_uint2(v.x, v.y);
            d2[1] = make_uint2(v.z, v.w);
        }
        __syncthreads();
#pragma unroll
        for (int round = 0; round < 3; ++round) {
            u32 baseA = (round == 2) ? baseAlo : baseAhi;
            u32 baseB = (round == 1) ? baseBlo : baseBhi;
#pragma unroll
            for (int ks = 0; ks < 2; ++ks) {
                u32 a[2][4];
#pragma unroll
                for (int mt = 0; mt < 2; mt++) {
                    int arow = wm * 32 + mt * 16 + laneRow;
                    u32 addr = baseA + (u32)((arow * APITCH + ks * 16 + laneK8) * 2);
                    ldmx4(a[mt][0], a[mt][1], a[mt][2], a[mt][3], addr);
                }
#pragma unroll
                for (int t = 0; t < 3; t++) {
                    int brow = wn * 48 + t * 16 + laneRow;
                    u32 addr = baseB + (u32)((brow * APITCH + ks * 16 + laneK8) * 2);
                    u32 b0, b1, b2, b3v;
                    ldmx4(b0, b1, b2, b3v, addr);
                    mma16816(acc[0][2 * t],     a[0], b0, b2);
                    mma16816(acc[0][2 * t + 1], a[0], b1, b3v);
                    mma16816(acc[1][2 * t],     a[1], b0, b2);
                    mma16816(acc[1][2 * t + 1], a[1], b1, b3v);
                }
            }
        }
    }

    // ---------------- epilogue ----------------
#pragma unroll
    for (int mt = 0; mt < 2; mt++) {
#pragma unroll
        for (int nt = 0; nt < 6; nt++) {
            int col = wn * 48 + nt * 8 + (lane & 3) * 2;
            int row = rbase + wm * 32 + mt * 16 + (lane >> 2);
            if (col < 40) {
                float b0 = s_b3[col], b1 = s_b3[col + 1];
                if (row < N_NODES)
                    *(float2*)(d_zs + (size_t)row * 40 + col) =
                        make_float2(acc[mt][nt][0] + b0, acc[mt][nt][1] + b1);
                if (row + 8 < N_NODES)
                    *(float2*)(d_zs + (size_t)(row + 8) * 40 + col) =
                        make_float2(acc[mt][nt][2] + b0, acc[mt][nt][3] + b1);
            } else if (col < 80) {
                int c = (col - 40) >> 1;
                if (row < N_NODES)
                    d_z40h[(size_t)row * 20 + c] =
                        h2u(__floats2half2_rn(acc[mt][nt][0], acc[mt][nt][1]));
                if (row + 8 < N_NODES)
                    d_z40h[(size_t)(row + 8) * 20 + c] =
                        h2u(__floats2half2_rn(acc[mt][nt][2], acc[mt][nt][3]));
            }
        }
    }
}

// ------------- layer-3 aggregation (40 ch, fp16 gather, MLP=4) + log_softmax --
__global__ void agg40_lsm(float* __restrict__ out) {
    int w = (blockIdx.x * blockDim.x + threadIdx.x) >> 5;
    if (w >= N_NODES) return;
    int lane = threadIdx.x & 31;
    bool act = lane < 20;                 // lane owns channels 2*lane, 2*lane+1
    int s = d_rowptr[w], e = d_rowptr[w + 1];
    float acc0 = 0.f, acc1 = 0.f, acc2 = 0.f, acc3 = 0.f;
    int i = s;
    for (; i + 3 < e; i += 4) {
        int s0 = d_csr[i], s1 = d_csr[i + 1], s2 = d_csr[i + 2], s3 = d_csr[i + 3];
        if (act) {
            u32 v0 = __ldg(d_z40h + (size_t)s0 * 20 + lane);
            u32 v1 = __ldg(d_z40h + (size_t)s1 * 20 + lane);
            u32 v2 = __ldg(d_z40h + (size_t)s2 * 20 + lane);
            u32 v3 = __ldg(d_z40h + (size_t)s3 * 20 + lane);
            float2 f0 = u2f(v0), f1 = u2f(v1), f2 = u2f(v2), f3 = u2f(v3);
            acc0 += f0.x + f1.x; acc1 += f0.y + f1.y;
            acc2 += f2.x + f3.x; acc3 += f2.y + f3.y;
        }
    }
    for (; i < e; i++) {
        if (act) {
            u32 v0 = __ldg(d_z40h + (size_t)d_csr[i] * 20 + lane);
            float2 f0 = u2f(v0);
            acc0 += f0.x; acc1 += f0.y;
        }
    }
    acc0 += acc2; acc1 += acc3;
    float inv = (e > s) ? 1.0f / (float)(e - s) : 0.0f;
    float v0 = -1e30f, v1 = -1e30f;
    if (act) {
        float2 zs = *(const float2*)(d_zs + (size_t)w * 40 + lane * 2);
        v0 = zs.x + acc0 * inv;
        v1 = zs.y + acc1 * inv;
    }
    float m = fmaxf(v0, v1);
#pragma unroll
    for (int off = 16; off > 0; off >>= 1)
        m = fmaxf(m, __shfl_xor_sync(0xffffffffu, m, off));
    float se = act ? (expf(v0 - m) + expf(v1 - m)) : 0.f;
#pragma unroll
    for (int off = 16; off > 0; off >>= 1)
        se += __shfl_xor_sync(0xffffffffu, se, off);
    float lse = m + logf(se);
    if (act) {
        *(float2*)(out + (size_t)w * 40 + lane * 2) = make_float2(v0 - lse, v1 - lse);
    }
}

// ---------------- launch (pure kernel launches) ----------------
extern "C" void kernel_launch(void* const* d_in, const int* in_sizes, int n_in,
                              void* d_out, int out_size) {
    const float* x   = (const float*)d_in[0];
    const int*   ei  = (const int*)d_in[1];
    const float* Ws1 = (const float*)d_in[2];
    const float* Wn1 = (const float*)d_in[3];
    const float* b1  = (const float*)d_in[4];
    const float* Ws2 = (const float*)d_in[5];
    const float* Wn2 = (const float*)d_in[6];
    const float* b2  = (const float*)d_in[7];
    const float* Ws3 = (const float*)d_in[8];
    const float* Wn3 = (const float*)d_in[9];
    const float* b3  = (const float*)d_in[10];
    const float* g1  = (const float*)d_in[11];
    const float* be1 = (const float*)d_in[12];
    const float* m1  = (const float*)d_in[13];
    const float* v1  = (const float*)d_in[14];
    const float* g2  = (const float*)d_in[15];
    const float* be2 = (const float*)d_in[16];
    const float* m2  = (const float*)d_in[17];
    const float* v2  = (const float*)d_in[18];
    float* out = (float*)d_out;

    const int* src = ei;
    const int* dst = ei + N_EDGES;

    // constants / weight images / x conversion
    prep_bn<<<1, 128>>>(b1, g1, be1, m1, v1, b2, g2, be2, m2, v2);
    prep_w<<<(4 * 16384 + 255) / 256, 256>>>(Ws1, Wn1, Ws2, Wn2);
    prep_w3<<<(2 * 4 * 96 * 32 + 255) / 256, 256>>>(Ws3, Wn3);
    conv_xh<<<(N_NODES * 32 + 255) / 256, 256>>>(x);

    // CSR build
    zero_counts<<<(N_NODES + 255) / 256, 256>>>();
    hist_kernel<<<(N_EDGES + 255) / 256, 256>>>(dst);
    scanA<<<SCAN_NB, 1024>>>();
    scanB<<<1, 32>>>();
    scanC<<<SCAN_NB, 1024>>>();
    fill_csr<<<(N_EDGES + 255) / 256, 256>>>(src, dst);

    const int gemm_blocks = (N_NODES + 127) / 128;     // 782
    const int agg_blocks  = (N_NODES + 7) / 8;

    // Layer 1
    agg128<0><<<agg_blocks, 256>>>();
    gemm_mma<1><<<gemm_blocks, 256>>>(x);
    // Layer 2
    agg128<1><<<agg_blocks, 256>>>();
    gemm_mma<2><<<gemm_blocks, 256>>>(nullptr);
    // Layer 3
    gemm80_mma<<<gemm_blocks, 256>>>(b3);
    agg40_lsm<<<agg_blocks, 256>>>(out);
}

// round 14
// speedup vs baseline: 1.0347x; 1.0347x over previous
#include <cuda_runtime.h>
#include <cuda_bf16.h>
#include <cuda_fp16.h>
#include <math.h>

#define N_NODES 100000
#define N_EDGES 1600000
#define HIDC    128
#define SCAN_NB 98

typedef unsigned int u32;
typedef unsigned long long u64;
typedef unsigned short u16;

// ---------------- device scratch (static globals; no allocation) ----------------
__device__ u32   d_aggb2[(size_t)N_NODES * HIDC];   // aggregated mean, bf16 pairs
__device__ u32   d_h1b2 [(size_t)N_NODES * HIDC];   // layer1 out bf16 pairs (gemm2 A)
__device__ u32   d_h2b2 [(size_t)N_NODES * HIDC];   // layer2 out bf16 pairs (gemm80 A)
__device__ u32   d_xh   [(size_t)N_NODES * 64];     // x   as fp16 (2/word)  - agg gather
__device__ u32   d_h1h  [(size_t)N_NODES * 64];     // h1  as fp16 (2/word)  - agg gather
__device__ float d_zs   [(size_t)N_NODES * 40];     // layer3 self+bias fp32
__device__ u32   d_z40h [(size_t)N_NODES * 20];     // layer3 neigh logits fp16
__device__ int   d_counts[N_NODES + 1];
__device__ int   d_rowptr[N_NODES + 1];
__device__ int   d_cursor[N_NODES];
__device__ int   d_csr[N_EDGES];
__device__ int   d_blocksum[SCAN_NB];
__device__ float d_scale1[HIDC], d_shift1[HIDC], d_scale2[HIDC], d_shift2[HIDC];
// layer-1/2 weight images: [layer*2+mat][split][n(128)][k(128)] bf16
__device__ __align__(16) u16 d_wimg[4 * 2 * 128 * 128];
// layer-3 weight image: [split(2)][ck(4)][n(96)][jj(32)]; n<40 Ws3, 40..79 Wn3, else 0
__device__ __align__(16) u16 d_wimg3[2 * 4 * 96 * 32];

// ---------------- helpers ----------------
__device__ __forceinline__ u32 smem_u32(const void* p) {
    u32 a;
    asm("{ .reg .u64 t; cvta.to.shared.u64 t, %1; cvt.u32.u64 %0, t; }" : "=r"(a) : "l"(p));
    return a;
}
// pack fp32 -> (lo_bf16<<16)|hi_bf16, truncation split
__device__ __forceinline__ u32 packb2(float f) {
    u32 t = __float_as_uint(f);
    float r = f - __uint_as_float(t & 0xFFFF0000u);
    return __byte_perm(t, __float_as_uint(r), 0x7632);
}
__device__ __forceinline__ void split16(float f, u16& h, u16& l) {
    u32 t = __float_as_uint(f);
    h = (u16)(t >> 16);
    float r = f - __uint_as_float(t & 0xFFFF0000u);
    l = (u16)(__float_as_uint(r) >> 16);
}
__device__ __forceinline__ u32 h2u(__half2 h) { return *reinterpret_cast<u32*>(&h); }
__device__ __forceinline__ float2 u2f(u32 v) {
    __half2 h = *reinterpret_cast<__half2*>(&v);
    return __half22float2(h);
}
__device__ __forceinline__ void ldmx4(u32& r0, u32& r1, u32& r2, u32& r3, u32 addr) {
    asm volatile("ldmatrix.sync.aligned.m8n8.x4.shared.b16 {%0,%1,%2,%3}, [%4];"
                 : "=r"(r0), "=r"(r1), "=r"(r2), "=r"(r3) : "r"(addr));
}
__device__ __forceinline__ void mma16816(float* d, const u32* a, u32 b0, u32 b1) {
    asm volatile("mma.sync.aligned.m16n8k16.row.col.f32.bf16.bf16.f32 "
                 "{%0,%1,%2,%3}, {%4,%5,%6,%7}, {%8,%9}, {%0,%1,%2,%3};"
                 : "+f"(d[0]), "+f"(d[1]), "+f"(d[2]), "+f"(d[3])
                 : "r"(a[0]), "r"(a[1]), "r"(a[2]), "r"(a[3]), "r"(b0), "r"(b1));
}

// ---------------- small prep kernels ----------------
__global__ void prep_bn(const float* b1, const float* g1, const float* be1,
                        const float* m1, const float* v1,
                        const float* b2, const float* g2, const float* be2,
                        const float* m2, const float* v2) {
    int c = threadIdx.x;
    if (c < HIDC) {
        float s1 = g1[c] * rsqrtf(v1[c] + 1e-5f);
        d_scale1[c] = s1; d_shift1[c] = (b1[c] - m1[c]) * s1 + be1[c];
        float s2 = g2[c] * rsqrtf(v2[c] + 1e-5f);
        d_scale2[c] = s2; d_shift2[c] = (b2[c] - m2[c]) * s2 + be2[c];
    }
}

// layer-1/2 weights -> hi/lo split images, transposed to [n][k]
__global__ void prep_w(const float* __restrict__ Ws1, const float* __restrict__ Wn1,
                       const float* __restrict__ Ws2, const float* __restrict__ Wn2) {
    int idx = blockIdx.x * 256 + threadIdx.x;       // 0 .. 4*16384-1
    if (idx >= 4 * 16384) return;
    int mat4 = idx >> 14;
    int e = idx & 16383;
    int k = e >> 7, n = e & 127;
    const float* W = (mat4 == 0) ? Ws1 : (mat4 == 1) ? Wn1 : (mat4 == 2) ? Ws2 : Wn2;
    u16 h, l; split16(W[k * 128 + n], h, l);
    d_wimg[((size_t)(mat4 * 2 + 0) * 128 + n) * 128 + k] = h;
    d_wimg[((size_t)(mat4 * 2 + 1) * 128 + n) * 128 + k] = l;
}

// layer-3 weights -> split image [split][ck][n96][jj32]
__global__ void prep_w3(const float* __restrict__ Ws3, const float* __restrict__ Wn3) {
    int idx = blockIdx.x * 256 + threadIdx.x;       // 0 .. 24575
    if (idx >= 2 * 4 * 96 * 32) return;
    int jj = idx & 31;
    int t2 = idx >> 5;
    int n = t2 % 96;
    int t3 = t2 / 96;
    int ck = t3 & 3;
    int split = t3 >> 2;
    int k = ck * 32 + jj;
    float w = 0.f;
    if (n < 40)      w = Ws3[k * 40 + n];
    else if (n < 80) w = Wn3[k * 40 + (n - 40)];
    u16 h, l; split16(w, h, l);
    d_wimg3[idx] = split ? l : h;
}

// x -> fp16 only (aggregation gather); gemm1 reads fp32 x directly
__global__ void conv_xh(const float* __restrict__ x) {
    int i = blockIdx.x * 256 + threadIdx.x;
    if (i < N_NODES * 32) {
        float4 v = ((const float4*)x)[i];
        uint2 hh;
        hh.x = h2u(__floats2half2_rn(v.x, v.y));
        hh.y = h2u(__floats2half2_rn(v.z, v.w));
        ((uint2*)d_xh)[i] = hh;
    }
}

// ---------------- CSR build ----------------
__global__ void zero_counts() {
    int i = blockIdx.x * blockDim.x + threadIdx.x;
    if (i < N_NODES) d_counts[i] = 0;
}
__global__ void hist_kernel(const int* __restrict__ dst) {
    int e = blockIdx.x * blockDim.x + threadIdx.x;
    if (e < N_EDGES) atomicAdd(&d_counts[dst[e]], 1);
}
__global__ void scanA() {
    __shared__ int sh[1024];
    int i = blockIdx.x * 1024 + threadIdx.x;
    sh[threadIdx.x] = (i < N_NODES) ? d_counts[i] : 0;
    __syncthreads();
    for (int s = 512; s > 0; s >>= 1) {
        if (threadIdx.x < s) sh[threadIdx.x] += sh[threadIdx.x + s];
        __syncthreads();
    }
    if (threadIdx.x == 0) d_blocksum[blockIdx.x] = sh[0];
}
__global__ void scanB() {
    if (threadIdx.x == 0) {
        int acc = 0;
        for (int b = 0; b < SCAN_NB; b++) { int t = d_blocksum[b]; d_blocksum[b] = acc; acc += t; }
    }
}
__global__ void scanC() {   // also seeds d_cursor
    __shared__ int sh[2][1024];
    int t = threadIdx.x;
    int i = blockIdx.x * 1024 + t;
    int v = (i < N_NODES) ? d_counts[i] : 0;
    sh[0][t] = v;
    __syncthreads();
    int cur = 0;
    for (int off = 1; off < 1024; off <<= 1) {
        int val = sh[cur][t];
        if (t >= off) val += sh[cur][t - off];
        sh[cur ^ 1][t] = val;
        cur ^= 1;
        __syncthreads();
    }
    int excl = sh[cur][t] - v + d_blocksum[blockIdx.x];
    if (i <= N_NODES) d_rowptr[i] = excl;
    if (i < N_NODES)  d_cursor[i] = excl;
}
__global__ void fill_csr(const int* __restrict__ src, const int* __restrict__ dst) {
    int e = blockIdx.x * blockDim.x + threadIdx.x;
    if (e < N_EDGES) {
        int d = dst[e];
        int p = atomicAdd(&d_cursor[d], 1);
        d_csr[p] = src[e];
    }
}

// ---------------- aggregation (warp per node, F=128), fp16 gather, MLP=2 ------
// SRC==0: d_xh.  SRC==1: d_h1h.  fp32 accumulate -> bf16-pair means out.
template<int SRC>
__global__ void agg128() {
    int w = (blockIdx.x * blockDim.x + threadIdx.x) >> 5;
    if (w >= N_NODES) return;
    const u32* __restrict__ xh = (SRC == 0) ? (const u32*)d_xh : (const u32*)d_h1h;
    int lane = threadIdx.x & 31;
    int s = d_rowptr[w], e = d_rowptr[w + 1];
    float4 a0 = make_float4(0.f, 0.f, 0.f, 0.f);
    float4 a1 = make_float4(0.f, 0.f, 0.f, 0.f);
    int i = s;
    for (; i + 1 < e; i += 2) {
        int s0 = d_csr[i], s1 = d_csr[i + 1];
        uint2 v0 = __ldg((const uint2*)(xh + (size_t)s0 * 64) + lane);
        uint2 v1 = __ldg((const uint2*)(xh + (size_t)s1 * 64) + lane);
        float2 f;
        f = u2f(v0.x); a0.x += f.x; a0.y += f.y;
        f = u2f(v0.y); a0.z += f.x; a0.w += f.y;
        f = u2f(v1.x); a1.x += f.x; a1.y += f.y;
        f = u2f(v1.y); a1.z += f.x; a1.w += f.y;
    }
    if (i < e) {
        int s0 = d_csr[i];
        uint2 v0 = __ldg((const uint2*)(xh + (size_t)s0 * 64) + lane);
        float2 f;
        f = u2f(v0.x); a0.x += f.x; a0.y += f.y;
        f = u2f(v0.y); a0.z += f.x; a0.w += f.y;
    }
    a0.x += a1.x; a0.y += a1.y; a0.z += a1.z; a0.w += a1.w;
    float inv = (e > s) ? 1.0f / (float)(e - s) : 0.0f;
    uint4 o;
    o.x = packb2(a0.x * inv); o.y = packb2(a0.y * inv);
    o.z = packb2(a0.z * inv); o.w = packb2(a0.w * inv);
    *((uint4*)(d_aggb2 + (size_t)w * HIDC) + lane) = o;
}

// ---------------- mma.sync fused two-input GEMM (layers 1 & 2) ----------------
// D = Aself@W1 + Aneigh@W2 via bf16 hi/lo 3-split, fp32 register accumulators.
// LAYER 1: Aself = fp32 x (split on the fly).  LAYER 2: Aself = d_h1b2 pairs.
#define APITCH 40   // bf16 pitch; 80B = 5 x 16B (odd mod 8 -> ldmatrix conflict-free)

template<int LAYER>
__global__ __launch_bounds__(256, 2) void gemm_mma(const float* __restrict__ xf) {
    __shared__ __align__(16) u16 sAhi[128 * APITCH];
    __shared__ __align__(16) u16 sAlo[128 * APITCH];
    __shared__ __align__(16) u16 sBhi[128 * APITCH];
    __shared__ __align__(16) u16 sBlo[128 * APITCH];
    __shared__ float s_sc[128], s_sh[128];

    int tid = threadIdx.x, lane = tid & 31, wid = tid >> 5;
    int wm = wid >> 1, wn = wid & 1;
    int rbase = blockIdx.x * 128;

    if (tid < 128) {
        s_sc[tid] = (LAYER == 1) ? d_scale1[tid] : d_scale2[tid];
        s_sh[tid] = (LAYER == 1) ? d_shift1[tid] : d_shift2[tid];
    }

    const u16* __restrict__ wL = d_wimg + (size_t)(LAYER - 1) * 2 * 2 * 16384;

    float acc[2][8][4];
#pragma unroll
    for (int mt = 0; mt < 2; mt++)
#pragma unroll
        for (int nt = 0; nt < 8; nt++)
#pragma unroll
            for (int r = 0; r < 4; r++) acc[mt][nt][r] = 0.f;

    int laneRow = (lane & 7) + ((lane >> 3) & 1) * 8;
    int laneK8  = (lane >> 4) * 8;
    u32 baseAhi = smem_u32(sAhi), baseAlo = smem_u32(sAlo);
    u32 baseBhi = smem_u32(sBhi), baseBlo = smem_u32(sBlo);

    for (int phase = 0; phase < 2; ++phase) {
        const u16* __restrict__ wimg = wL + (size_t)phase * 2 * 16384;
        for (int ck = 0; ck < 4; ++ck) {
            __syncthreads();
            // ---- A chunk (128 rows x 32 k) ----
#pragma unroll
            for (int i = 0; i < 4; i++) {
                int idx = tid + i * 256;
                int row = idx >> 3, q = idx & 7;
                int grow = rbase + row; if (grow >= N_NODES) grow = N_NODES - 1;
                u32* dh = (u32*)sAhi + row * (APITCH / 2) + q * 2;
                u32* dl = (u32*)sAlo + row * (APITCH / 2) + q * 2;
                if (LAYER == 1 && phase == 0) {
                    // fp32 x: split on the fly
                    float4 v = *(const float4*)(xf + (size_t)grow * HIDC + ck * 32 + q * 4);
                    u32 t0 = __float_as_uint(v.x), t1 = __float_as_uint(v.y);
                    u32 t2 = __float_as_uint(v.z), t3 = __float_as_uint(v.w);
                    float r0 = v.x - __uint_as_float(t0 & 0xFFFF0000u);
                    float r1 = v.y - __uint_as_float(t1 & 0xFFFF0000u);
                    float r2 = v.z - __uint_as_float(t2 & 0xFFFF0000u);
                    float r3 = v.w - __uint_as_float(t3 & 0xFFFF0000u);
                    dh[0] = __byte_perm(t0, t1, 0x7632);
                    dh[1] = __byte_perm(t2, t3, 0x7632);
                    dl[0] = __byte_perm(__float_as_uint(r0), __float_as_uint(r1), 0x7632);
                    dl[1] = __byte_perm(__float_as_uint(r2), __float_as_uint(r3), 0x7632);
                } else {
                    const u32* Apair = phase ? (const u32*)d_aggb2 : (const u32*)d_h1b2;
                    uint4 v = *(const uint4*)(Apair + (size_t)grow * HIDC + ck * 32 + q * 4);
                    dh[0] = __byte_perm(v.x, v.y, 0x5410);
                    dh[1] = __byte_perm(v.z, v.w, 0x5410);
                    dl[0] = __byte_perm(v.x, v.y, 0x7632);
                    dl[1] = __byte_perm(v.z, v.w, 0x7632);
                }
            }
#pragma unroll
            for (int i = 0; i < 4; i++) {
                int idx = tid + i * 256;
                int split = idx >> 9, r = idx & 511;
                int row = r >> 2, q = r & 3;
                uint4 v = *((const uint4*)(wimg + ((size_t)split * 128 + row) * 128 + ck * 32) + q);
                u16* dstb = split ? sBlo : sBhi;
                uint2* d2 = (uint2*)(dstb + row * APITCH + q * 8);
                d2[0] = make_uint2(v.x, v.y);
                d2[1] = make_uint2(v.z, v.w);
            }
            __syncthreads();
#pragma unroll
            for (int round = 0; round < 3; ++round) {
                u32 baseA = (round == 2) ? baseAlo : baseAhi;
                u32 baseB = (round == 1) ? baseBlo : baseBhi;
#pragma unroll
                for (int ks = 0; ks < 2; ++ks) {
                    u32 a[2][4];
#pragma unroll
                    for (int mt = 0; mt < 2; mt++) {
                        int arow = wm * 32 + mt * 16 + laneRow;
                        u32 addr = baseA + (u32)((arow * APITCH + ks * 16 + laneK8) * 2);
                        ldmx4(a[mt][0], a[mt][1], a[mt][2], a[mt][3], addr);
                    }
#pragma unroll
                    for (int t = 0; t < 4; t++) {
                        int brow = wn * 64 + t * 16 + laneRow;
                        u32 addr = baseB + (u32)((brow * APITCH + ks * 16 + laneK8) * 2);
                        u32 b0, b1, b2, b3;
                        ldmx4(b0, b1, b2, b3, addr);
                        mma16816(acc[0][2 * t],     a[0], b0, b2);
                        mma16816(acc[0][2 * t + 1], a[0], b1, b3);
                        mma16816(acc[1][2 * t],     a[1], b0, b2);
                        mma16816(acc[1][2 * t + 1], a[1], b1, b3);
                    }
                }
            }
        }
    }

    // ---------------- epilogue: BN + ReLU -> bf16 pairs (+ fp16 for LAYER 1) ---
    u32* __restrict__ OUTP = (LAYER == 1) ? d_h1b2 : d_h2b2;
#pragma unroll
    for (int mt = 0; mt < 2; mt++) {
#pragma unroll
        for (int nt = 0; nt < 8; nt++) {
            int col = wn * 64 + nt * 8 + (lane & 3) * 2;
            float sc0 = s_sc[col], sc1 = s_sc[col + 1];
            float sh0 = s_sh[col], sh1 = s_sh[col + 1];
            int row = rbase + wm * 32 + mt * 16 + (lane >> 2);
            float v0 = fmaxf(fmaf(acc[mt][nt][0], sc0, sh0), 0.f);
            float v1 = fmaxf(fmaf(acc[mt][nt][1], sc1, sh1), 0.f);
            float v2 = fmaxf(fmaf(acc[mt][nt][2], sc0, sh0), 0.f);
            float v3 = fmaxf(fmaf(acc[mt][nt][3], sc1, sh1), 0.f);
            if (row < N_NODES) {
                *(uint2*)(OUTP + (size_t)row * HIDC + col) =
                    make_uint2(packb2(v0), packb2(v1));
                if (LAYER == 1)
                    d_h1h[(size_t)row * 64 + (col >> 1)] = h2u(__floats2half2_rn(v0, v1));
            }
            if (row + 8 < N_NODES) {
                *(uint2*)(OUTP + (size_t)(row + 8) * HIDC + col) =
                    make_uint2(packb2(v2), packb2(v3));
                if (LAYER == 1)
                    d_h1h[(size_t)(row + 8) * 64 + (col >> 1)] = h2u(__floats2half2_rn(v2, v3));
            }
        }
    }
}

// ---------------- layer-3 GEMM (mma.sync, 3-split) ----------------------------
// CTA tile 128 x 96 (cols 80..95 zero-pad), 8 warps 4(m)x2(n), 48 cols/warp.
// Epilogue: self cols -> d_zs fp32 (+bias); neigh cols -> d_z40h fp16.
__global__ __launch_bounds__(256, 2) void gemm80_mma(const float* __restrict__ b3) {
    __shared__ __align__(16) u16 sAhi[128 * APITCH];
    __shared__ __align__(16) u16 sAlo[128 * APITCH];
    __shared__ __align__(16) u16 sBhi[96 * APITCH];
    __shared__ __align__(16) u16 sBlo[96 * APITCH];
    __shared__ float s_b3[40];

    int tid = threadIdx.x, lane = tid & 31, wid = tid >> 5;
    int wm = wid >> 1, wn = wid & 1;
    int rbase = blockIdx.x * 128;

    if (tid < 40) s_b3[tid] = b3[tid];

    float acc[2][6][4];
#pragma unroll
    for (int mt = 0; mt < 2; mt++)
#pragma unroll
        for (int nt = 0; nt < 6; nt++)
#pragma unroll
            for (int r = 0; r < 4; r++) acc[mt][nt][r] = 0.f;

    int laneRow = (lane & 7) + ((lane >> 3) & 1) * 8;
    int laneK8  = (lane >> 4) * 8;
    u32 baseAhi = smem_u32(sAhi), baseAlo = smem_u32(sAlo);
    u32 baseBhi = smem_u32(sBhi), baseBlo = smem_u32(sBlo);

    for (int ck = 0; ck < 4; ++ck) {
        __syncthreads();
#pragma unroll
        for (int i = 0; i < 4; i++) {
            int idx = tid + i * 256;
            int row = idx >> 3, q = idx & 7;
            int grow = rbase + row; if (grow >= N_NODES) grow = N_NODES - 1;
            uint4 v = *(const uint4*)((const u32*)d_h2b2 + (size_t)grow * HIDC + ck * 32 + q * 4);
            u32* dh = (u32*)sAhi + row * (APITCH / 2) + q * 2;
            u32* dl = (u32*)sAlo + row * (APITCH / 2) + q * 2;
            dh[0] = __byte_perm(v.x, v.y, 0x5410);
            dh[1] = __byte_perm(v.z, v.w, 0x5410);
            dl[0] = __byte_perm(v.x, v.y, 0x7632);
            dl[1] = __byte_perm(v.z, v.w, 0x7632);
        }
#pragma unroll
        for (int i = 0; i < 3; i++) {
            int idx = tid + i * 256;        // 0..767
            int split = idx / 384, r = idx % 384;
            int row = r >> 2, q = r & 3;
            uint4 v = *((const uint4*)(d_wimg3 + ((size_t)(split * 4 + ck) * 96 + row) * 32) + q);
            u16* dstb = split ? sBlo : sBhi;
            uint2* d2 = (uint2*)(dstb + row * APITCH + q * 8);
            d2[0] = make_uint2(v.x, v.y);
            d2[1] = make_uint2(v.z, v.w);
        }
        __syncthreads();
#pragma unroll
        for (int round = 0; round < 3; ++round) {
            u32 baseA = (round == 2) ? baseAlo : baseAhi;
            u32 baseB = (round == 1) ? baseBlo : baseBhi;
#pragma unroll
            for (int ks = 0; ks < 2; ++ks) {
                u32 a[2][4];
#pragma unroll
                for (int mt = 0; mt < 2; mt++) {
                    int arow = wm * 32 + mt * 16 + laneRow;
                    u32 addr = baseA + (u32)((arow * APITCH + ks * 16 + laneK8) * 2);
                    ldmx4(a[mt][0], a[mt][1], a[mt][2], a[mt][3], addr);
                }
#pragma unroll
                for (int t = 0; t < 3; t++) {
                    int brow = wn * 48 + t * 16 + laneRow;
                    u32 addr = baseB + (u32)((brow * APITCH + ks * 16 + laneK8) * 2);
                    u32 b0, b1, b2, b3v;
                    ldmx4(b0, b1, b2, b3v, addr);
                    mma16816(acc[0][2 * t],     a[0], b0, b2);
                    mma16816(acc[0][2 * t + 1], a[0], b1, b3v);
                    mma16816(acc[1][2 * t],     a[1], b0, b2);
                    mma16816(acc[1][2 * t + 1], a[1], b1, b3v);
                }
            }
        }
    }

    // ---------------- epilogue ----------------
#pragma unroll
    for (int mt = 0; mt < 2; mt++) {
#pragma unroll
        for (int nt = 0; nt < 6; nt++) {
            int col = wn * 48 + nt * 8 + (lane & 3) * 2;
            int row = rbase + wm * 32 + mt * 16 + (lane >> 2);
            if (col < 40) {
                float b0 = s_b3[col], b1 = s_b3[col + 1];
                if (row < N_NODES)
                    *(float2*)(d_zs + (size_t)row * 40 + col) =
                        make_float2(acc[mt][nt][0] + b0, acc[mt][nt][1] + b1);
                if (row + 8 < N_NODES)
                    *(float2*)(d_zs + (size_t)(row + 8) * 40 + col) =
                        make_float2(acc[mt][nt][2] + b0, acc[mt][nt][3] + b1);
            } else if (col < 80) {
                int c = (col - 40) >> 1;
                if (row < N_NODES)
                    d_z40h[(size_t)row * 20 + c] =
                        h2u(__floats2half2_rn(acc[mt][nt][0], acc[mt][nt][1]));
                if (row + 8 < N_NODES)
                    d_z40h[(size_t)(row + 8) * 20 + c] =
                        h2u(__floats2half2_rn(acc[mt][nt][2], acc[mt][nt][3]));
            }
        }
    }
}

// ------------- layer-3 aggregation (40 ch, fp16 gather) + log_softmax ---------
__global__ void agg40_lsm(float* __restrict__ out) {
    int w = (blockIdx.x * blockDim.x + threadIdx.x) >> 5;
    if (w >= N_NODES) return;
    int lane = threadIdx.x & 31;
    bool act = lane < 20;                 // lane owns channels 2*lane, 2*lane+1
    int s = d_rowptr[w], e = d_rowptr[w + 1];
    float acc0 = 0.f, acc1 = 0.f;
    int i = s;
    for (; i + 1 < e; i += 2) {
        int s0 = d_csr[i], s1 = d_csr[i + 1];
        if (act) {
            u32 v0 = __ldg(d_z40h + (size_t)s0 * 20 + lane);
            u32 v1 = __ldg(d_z40h + (size_t)s1 * 20 + lane);
            float2 f0 = u2f(v0), f1 = u2f(v1);
            acc0 += f0.x + f1.x; acc1 += f0.y + f1.y;
        }
    }
    if (i < e && act) {
        u32 v0 = __ldg(d_z40h + (size_t)d_csr[i] * 20 + lane);
        float2 f0 = u2f(v0);
        acc0 += f0.x; acc1 += f0.y;
    }
    float inv = (e > s) ? 1.0f / (float)(e - s) : 0.0f;
    float v0 = -1e30f, v1 = -1e30f;
    if (act) {
        float2 zs = *(const float2*)(d_zs + (size_t)w * 40 + lane * 2);
        v0 = zs.x + acc0 * inv;
        v1 = zs.y + acc1 * inv;
    }
    float m = fmaxf(v0, v1);
#pragma unroll
    for (int off = 16; off > 0; off >>= 1)
        m = fmaxf(m, __shfl_xor_sync(0xffffffffu, m, off));
    float se = act ? (expf(v0 - m) + expf(v1 - m)) : 0.f;
#pragma unroll
    for (int off = 16; off > 0; off >>= 1)
        se += __shfl_xor_sync(0xffffffffu, se, off);
    float lse = m + logf(se);
    if (act) {
        *(float2*)(out + (size_t)w * 40 + lane * 2) = make_float2(v0 - lse, v1 - lse);
    }
}

// ---------------- launch (pure kernel launches) ----------------
extern "C" void kernel_launch(void* const* d_in, const int* in_sizes, int n_in,
                              void* d_out, int out_size) {
    const float* x   = (const float*)d_in[0];
    const int*   ei  = (const int*)d_in[1];
    const float* Ws1 = (const float*)d_in[2];
    const float* Wn1 = (const float*)d_in[3];
    const float* b1  = (const float*)d_in[4];
    const float* Ws2 = (const float*)d_in[5];
    const float* Wn2 = (const float*)d_in[6];
    const float* b2  = (const float*)d_in[7];
    const float* Ws3 = (const float*)d_in[8];
    const float* Wn3 = (const float*)d_in[9];
    const float* b3  = (const float*)d_in[10];
    const float* g1  = (const float*)d_in[11];
    const float* be1 = (const float*)d_in[12];
    const float* m1  = (const float*)d_in[13];
    const float* v1  = (const float*)d_in[14];
    const float* g2  = (const float*)d_in[15];
    const float* be2 = (const float*)d_in[16];
    const float* m2  = (const float*)d_in[17];
    const float* v2  = (const float*)d_in[18];
    float* out = (float*)d_out;

    const int* src = ei;
    const int* dst = ei + N_EDGES;

    // constants / weight images / x conversion
    prep_bn<<<1, 128>>>(b1, g1, be1, m1, v1, b2, g2, be2, m2, v2);
    prep_w<<<(4 * 16384 + 255) / 256, 256>>>(Ws1, Wn1, Ws2, Wn2);
    prep_w3<<<(2 * 4 * 96 * 32 + 255) / 256, 256>>>(Ws3, Wn3);
    conv_xh<<<(N_NODES * 32 + 255) / 256, 256>>>(x);

    // CSR build
    zero_counts<<<(N_NODES + 255) / 256, 256>>>();
    hist_kernel<<<(N_EDGES + 255) / 256, 256>>>(dst);
    scanA<<<SCAN_NB, 1024>>>();
    scanB<<<1, 32>>>();
    scanC<<<SCAN_NB, 1024>>>();
    fill_csr<<<(N_EDGES + 255) / 256, 256>>>(src, dst);

    const int gemm_blocks = (N_NODES + 127) / 128;     // 782
    const int agg_blocks  = (N_NODES + 7) / 8;

    // Layer 1
    agg128<0><<<agg_blocks, 256>>>();
    gemm_mma<1><<<gemm_blocks, 256>>>(x);
    // Layer 2
    agg128<1><<<agg_blocks, 256>>>();
    gemm_mma<2><<<gemm_blocks, 256>>>(nullptr);
    // Layer 3
    gemm80_mma<<<gemm_blocks, 256>>>(b3);
    agg40_lsm<<<agg_blocks, 256>>>(out);
}

// round 15
// speedup vs baseline: 1.0706x; 1.0347x over previous
#include <cuda_runtime.h>
#include <cuda_bf16.h>
#include <cuda_fp16.h>
#include <math.h>

#define N_NODES 100000
#define N_EDGES 1600000
#define HIDC    128
#define SCAN_NB 98

typedef unsigned int u32;
typedef unsigned long long u64;
typedef unsigned short u16;

// ---------------- device scratch (static globals; no allocation) ----------------
__device__ u32   d_aggb2[(size_t)N_NODES * HIDC];   // aggregated mean, bf16 pairs
__device__ u32   d_h1b2 [(size_t)N_NODES * HIDC];   // layer1 out bf16 pairs (gemm2 A)
__device__ u32   d_h2b2 [(size_t)N_NODES * HIDC];   // layer2 out bf16 pairs (gemm80 A)
__device__ u32   d_xh   [(size_t)N_NODES * 64];     // x   as fp16 (2/word)  - agg gather
__device__ u32   d_h1h  [(size_t)N_NODES * 64];     // h1  as fp16 (2/word)  - agg gather
__device__ float d_zs   [(size_t)N_NODES * 40];     // layer3 self+bias fp32
__device__ u32   d_z40h [(size_t)N_NODES * 20];     // layer3 neigh logits fp16
__device__ int   d_counts[N_NODES + 1];
__device__ int   d_rowptr[N_NODES + 1];
__device__ int   d_cursor[N_NODES];
__device__ int   d_csr[N_EDGES];
__device__ int   d_blocksum[SCAN_NB];
__device__ float d_scale1[HIDC], d_shift1[HIDC], d_scale2[HIDC], d_shift2[HIDC];
// layer-1/2 weight images: [layer*2+mat][split][n(128)][k(128)] bf16
__device__ __align__(16) u16 d_wimg[4 * 2 * 128 * 128];
// layer-3 weight image: [split(2)][ck(4)][n(96)][jj(32)]; n<40 Ws3, 40..79 Wn3, else 0
__device__ __align__(16) u16 d_wimg3[2 * 4 * 96 * 32];

// ---------------- helpers ----------------
__device__ __forceinline__ u32 smem_u32(const void* p) {
    u32 a;
    asm("{ .reg .u64 t; cvta.to.shared.u64 t, %1; cvt.u32.u64 %0, t; }" : "=r"(a) : "l"(p));
    return a;
}
// pack fp32 -> (lo_bf16<<16)|hi_bf16, truncation split
__device__ __forceinline__ u32 packb2(float f) {
    u32 t = __float_as_uint(f);
    float r = f - __uint_as_float(t & 0xFFFF0000u);
    return __byte_perm(t, __float_as_uint(r), 0x7632);
}
__device__ __forceinline__ void split16(float f, u16& h, u16& l) {
    u32 t = __float_as_uint(f);
    h = (u16)(t >> 16);
    float r = f - __uint_as_float(t & 0xFFFF0000u);
    l = (u16)(__float_as_uint(r) >> 16);
}
__device__ __forceinline__ u32 h2u(__half2 h) { return *reinterpret_cast<u32*>(&h); }
__device__ __forceinline__ float2 u2f(u32 v) {
    __half2 h = *reinterpret_cast<__half2*>(&v);
    return __half22float2(h);
}
__device__ __forceinline__ void cp16(u32 smem, const void* g) {
    asm volatile("cp.async.cg.shared.global [%0], [%1], 16;" :: "r"(smem), "l"(g) : "memory");
}
__device__ __forceinline__ void cp_commit_wait0() {
    asm volatile("cp.async.commit_group;" ::: "memory");
    asm volatile("cp.async.wait_group 0;" ::: "memory");
}
__device__ __forceinline__ void ldmx4(u32& r0, u32& r1, u32& r2, u32& r3, u32 addr) {
    asm volatile("ldmatrix.sync.aligned.m8n8.x4.shared.b16 {%0,%1,%2,%3}, [%4];"
                 : "=r"(r0), "=r"(r1), "=r"(r2), "=r"(r3) : "r"(addr));
}
__device__ __forceinline__ void mma16816(float* d, const u32* a, u32 b0, u32 b1) {
    asm volatile("mma.sync.aligned.m16n8k16.row.col.f32.bf16.bf16.f32 "
                 "{%0,%1,%2,%3}, {%4,%5,%6,%7}, {%8,%9}, {%0,%1,%2,%3};"
                 : "+f"(d[0]), "+f"(d[1]), "+f"(d[2]), "+f"(d[3])
                 : "r"(a[0]), "r"(a[1]), "r"(a[2]), "r"(a[3]), "r"(b0), "r"(b1));
}

// ---------------- merged prep kernel (one launch) ----------------
// regions: [0,12500) conv_xh | [12500,12891) zero_counts | [12891,13147) prep_w
//          [13147,13243) prep_w3 | [13243] prep_bn
#define PREP_BLOCKS (12500 + 391 + 256 + 96 + 1)
__global__ void prep_all(const float* __restrict__ x,
                         const float* __restrict__ Ws1, const float* __restrict__ Wn1,
                         const float* __restrict__ Ws2, const float* __restrict__ Wn2,
                         const float* __restrict__ Ws3, const float* __restrict__ Wn3,
                         const float* b1, const float* g1, const float* be1,
                         const float* m1, const float* v1,
                         const float* b2, const float* g2, const float* be2,
                         const float* m2, const float* v2) {
    int b = blockIdx.x;
    if (b < 12500) {
        int i = b * 256 + threadIdx.x;
        if (i < N_NODES * 32) {
            float4 v = ((const float4*)x)[i];
            uint2 hh;
            hh.x = h2u(__floats2half2_rn(v.x, v.y));
            hh.y = h2u(__floats2half2_rn(v.z, v.w));
            ((uint2*)d_xh)[i] = hh;
        }
    } else if (b < 12891) {
        int i = (b - 12500) * 256 + threadIdx.x;
        if (i < N_NODES) d_counts[i] = 0;
    } else if (b < 13147) {
        int idx = (b - 12891) * 256 + threadIdx.x;
        if (idx < 4 * 16384) {
            int mat4 = idx >> 14;
            int e = idx & 16383;
            int k = e >> 7, n = e & 127;
            const float* W = (mat4 == 0) ? Ws1 : (mat4 == 1) ? Wn1 : (mat4 == 2) ? Ws2 : Wn2;
            u16 h, l; split16(W[k * 128 + n], h, l);
            d_wimg[((size_t)(mat4 * 2 + 0) * 128 + n) * 128 + k] = h;
            d_wimg[((size_t)(mat4 * 2 + 1) * 128 + n) * 128 + k] = l;
        }
    } else if (b < 13243) {
        int idx = (b - 13147) * 256 + threadIdx.x;
        if (idx < 2 * 4 * 96 * 32) {
            int jj = idx & 31;
            int t2 = idx >> 5;
            int n = t2 % 96;
            int t3 = t2 / 96;
            int ck = t3 & 3;
            int split = t3 >> 2;
            int k = ck * 32 + jj;
            float w = 0.f;
            if (n < 40)      w = Ws3[k * 40 + n];
            else if (n < 80) w = Wn3[k * 40 + (n - 40)];
            u16 h, l; split16(w, h, l);
            d_wimg3[idx] = split ? l : h;
        }
    } else {
        int c = threadIdx.x;
        if (c < HIDC) {
            float s1 = g1[c] * rsqrtf(v1[c] + 1e-5f);
            d_scale1[c] = s1; d_shift1[c] = (b1[c] - m1[c]) * s1 + be1[c];
            float s2 = g2[c] * rsqrtf(v2[c] + 1e-5f);
            d_scale2[c] = s2; d_shift2[c] = (b2[c] - m2[c]) * s2 + be2[c];
        }
    }
}

// ---------------- CSR build ----------------
__global__ void hist_kernel(const int* __restrict__ dst) {
    int e = blockIdx.x * blockDim.x + threadIdx.x;
    if (e < N_EDGES) atomicAdd(&d_counts[dst[e]], 1);
}
__global__ void scanA() {
    __shared__ int sh[1024];
    int i = blockIdx.x * 1024 + threadIdx.x;
    sh[threadIdx.x] = (i < N_NODES) ? d_counts[i] : 0;
    __syncthreads();
    for (int s = 512; s > 0; s >>= 1) {
        if (threadIdx.x < s) sh[threadIdx.x] += sh[threadIdx.x + s];
        __syncthreads();
    }
    if (threadIdx.x == 0) d_blocksum[blockIdx.x] = sh[0];
}
__global__ void scanB() {
    if (threadIdx.x == 0) {
        int acc = 0;
        for (int b = 0; b < SCAN_NB; b++) { int t = d_blocksum[b]; d_blocksum[b] = acc; acc += t; }
    }
}
__global__ void scanC() {   // also seeds d_cursor
    __shared__ int sh[2][1024];
    int t = threadIdx.x;
    int i = blockIdx.x * 1024 + t;
    int v = (i < N_NODES) ? d_counts[i] : 0;
    sh[0][t] = v;
    __syncthreads();
    int cur = 0;
    for (int off = 1; off < 1024; off <<= 1) {
        int val = sh[cur][t];
        if (t >= off) val += sh[cur][t - off];
        sh[cur ^ 1][t] = val;
        cur ^= 1;
        __syncthreads();
    }
    int excl = sh[cur][t] - v + d_blocksum[blockIdx.x];
    if (i <= N_NODES) d_rowptr[i] = excl;
    if (i < N_NODES)  d_cursor[i] = excl;
}
__global__ void fill_csr(const int* __restrict__ src, const int* __restrict__ dst) {
    int e = blockIdx.x * blockDim.x + threadIdx.x;
    if (e < N_EDGES) {
        int d = dst[e];
        int p = atomicAdd(&d_cursor[d], 1);
        d_csr[p] = src[e];
    }
}

// ---------------- aggregation (warp per node, F=128), fp16 gather, MLP=2 ------
// SRC==0: d_xh.  SRC==1: d_h1h.  fp32 accumulate -> bf16-pair means out.
template<int SRC>
__global__ void agg128() {
    int w = (blockIdx.x * blockDim.x + threadIdx.x) >> 5;
    if (w >= N_NODES) return;
    const u32* __restrict__ xh = (SRC == 0) ? (const u32*)d_xh : (const u32*)d_h1h;
    int lane = threadIdx.x & 31;
    int s = d_rowptr[w], e = d_rowptr[w + 1];
    float4 a0 = make_float4(0.f, 0.f, 0.f, 0.f);
    float4 a1 = make_float4(0.f, 0.f, 0.f, 0.f);
    int i = s;
    for (; i + 1 < e; i += 2) {
        int s0 = d_csr[i], s1 = d_csr[i + 1];
        uint2 v0 = __ldg((const uint2*)(xh + (size_t)s0 * 64) + lane);
        uint2 v1 = __ldg((const uint2*)(xh + (size_t)s1 * 64) + lane);
        float2 f;
        f = u2f(v0.x); a0.x += f.x; a0.y += f.y;
        f = u2f(v0.y); a0.z += f.x; a0.w += f.y;
        f = u2f(v1.x); a1.x += f.x; a1.y += f.y;
        f = u2f(v1.y); a1.z += f.x; a1.w += f.y;
    }
    if (i < e) {
        int s0 = d_csr[i];
        uint2 v0 = __ldg((const uint2*)(xh + (size_t)s0 * 64) + lane);
        float2 f;
        f = u2f(v0.x); a0.x += f.x; a0.y += f.y;
        f = u2f(v0.y); a0.z += f.x; a0.w += f.y;
    }
    a0.x += a1.x; a0.y += a1.y; a0.z += a1.z; a0.w += a1.w;
    float inv = (e > s) ? 1.0f / (float)(e - s) : 0.0f;
    uint4 o;
    o.x = packb2(a0.x * inv); o.y = packb2(a0.y * inv);
    o.z = packb2(a0.z * inv); o.w = packb2(a0.w * inv);
    *((uint4*)(d_aggb2 + (size_t)w * HIDC) + lane) = o;
}

// ---------------- mma.sync fused two-input GEMM (layers 1 & 2) ----------------
// D = Aself@W1 + Aneigh@W2 via bf16 hi/lo 3-split, fp32 register accumulators.
// LAYER 1: Aself = fp32 x (split on the fly).  LAYER 2: Aself = d_h1b2 pairs.
// B staging via cp.async (16B contiguous chunks), issued before A staging.
#define APITCH 40   // bf16 pitch; 80B = 5 x 16B (odd mod 8 -> ldmatrix conflict-free)

template<int LAYER>
__global__ __launch_bounds__(256, 2) void gemm_mma(const float* __restrict__ xf) {
    __shared__ __align__(16) u16 sAhi[128 * APITCH];
    __shared__ __align__(16) u16 sAlo[128 * APITCH];
    __shared__ __align__(16) u16 sBhi[128 * APITCH];
    __shared__ __align__(16) u16 sBlo[128 * APITCH];
    __shared__ float s_sc[128], s_sh[128];

    int tid = threadIdx.x, lane = tid & 31, wid = tid >> 5;
    int wm = wid >> 1, wn = wid & 1;
    int rbase = blockIdx.x * 128;

    if (tid < 128) {
        s_sc[tid] = (LAYER == 1) ? d_scale1[tid] : d_scale2[tid];
        s_sh[tid] = (LAYER == 1) ? d_shift1[tid] : d_shift2[tid];
    }

    const u16* __restrict__ wL = d_wimg + (size_t)(LAYER - 1) * 2 * 2 * 16384;

    float acc[2][8][4];
#pragma unroll
    for (int mt = 0; mt < 2; mt++)
#pragma unroll
        for (int nt = 0; nt < 8; nt++)
#pragma unroll
            for (int r = 0; r < 4; r++) acc[mt][nt][r] = 0.f;

    int laneRow = (lane & 7) + ((lane >> 3) & 1) * 8;
    int laneK8  = (lane >> 4) * 8;
    u32 baseAhi = smem_u32(sAhi), baseAlo = smem_u32(sAlo);
    u32 baseBhi = smem_u32(sBhi), baseBlo = smem_u32(sBlo);

    for (int phase = 0; phase < 2; ++phase) {
        const u16* __restrict__ wimg = wL + (size_t)phase * 2 * 16384;
        for (int ck = 0; ck < 4; ++ck) {
            __syncthreads();
            // ---- B chunk via cp.async (issued first, overlaps A staging) ----
#pragma unroll
            for (int i = 0; i < 4; i++) {
                int idx = tid + i * 256;
                int split = idx >> 9, r = idx & 511;
                int row = r >> 2, q = r & 3;
                const void* g = wimg + ((size_t)split * 128 + row) * 128 + ck * 32 + q * 8;
                u16* dstb = split ? sBlo : sBhi;
                cp16(smem_u32(dstb + row * APITCH + q * 8), g);
            }
            // ---- A chunk (128 rows x 32 k) ----
#pragma unroll
            for (int i = 0; i < 4; i++) {
                int idx = tid + i * 256;
                int row = idx >> 3, q = idx & 7;
                int grow = rbase + row; if (grow >= N_NODES) grow = N_NODES - 1;
                u32* dh = (u32*)sAhi + row * (APITCH / 2) + q * 2;
                u32* dl = (u32*)sAlo + row * (APITCH / 2) + q * 2;
                if (LAYER == 1 && phase == 0) {
                    float4 v = *(const float4*)(xf + (size_t)grow * HIDC + ck * 32 + q * 4);
                    u32 t0 = __float_as_uint(v.x), t1 = __float_as_uint(v.y);
                    u32 t2 = __float_as_uint(v.z), t3 = __float_as_uint(v.w);
                    float r0 = v.x - __uint_as_float(t0 & 0xFFFF0000u);
                    float r1 = v.y - __uint_as_float(t1 & 0xFFFF0000u);
                    float r2 = v.z - __uint_as_float(t2 & 0xFFFF0000u);
                    float r3 = v.w - __uint_as_float(t3 & 0xFFFF0000u);
                    dh[0] = __byte_perm(t0, t1, 0x7632);
                    dh[1] = __byte_perm(t2, t3, 0x7632);
                    dl[0] = __byte_perm(__float_as_uint(r0), __float_as_uint(r1), 0x7632);
                    dl[1] = __byte_perm(__float_as_uint(r2), __float_as_uint(r3), 0x7632);
                } else {
                    const u32* Apair = phase ? (const u32*)d_aggb2 : (const u32*)d_h1b2;
                    uint4 v = *(const uint4*)(Apair + (size_t)grow * HIDC + ck * 32 + q * 4);
                    dh[0] = __byte_perm(v.x, v.y, 0x5410);
                    dh[1] = __byte_perm(v.z, v.w, 0x5410);
                    dl[0] = __byte_perm(v.x, v.y, 0x7632);
                    dl[1] = __byte_perm(v.z, v.w, 0x7632);
                }
            }
            cp_commit_wait0();
            __syncthreads();
#pragma unroll
            for (int round = 0; round < 3; ++round) {
                u32 baseA = (round == 2) ? baseAlo : baseAhi;
                u32 baseB = (round == 1) ? baseBlo : baseBhi;
#pragma unroll
                for (int ks = 0; ks < 2; ++ks) {
                    u32 a[2][4];
#pragma unroll
                    for (int mt = 0; mt < 2; mt++) {
                        int arow = wm * 32 + mt * 16 + laneRow;
                        u32 addr = baseA + (u32)((arow * APITCH + ks * 16 + laneK8) * 2);
                        ldmx4(a[mt][0], a[mt][1], a[mt][2], a[mt][3], addr);
                    }
#pragma unroll
                    for (int t = 0; t < 4; t++) {
                        int brow = wn * 64 + t * 16 + laneRow;
                        u32 addr = baseB + (u32)((brow * APITCH + ks * 16 + laneK8) * 2);
                        u32 b0, b1, b2, b3;
                        ldmx4(b0, b1, b2, b3, addr);
                        mma16816(acc[0][2 * t],     a[0], b0, b2);
                        mma16816(acc[0][2 * t + 1], a[0], b1, b3);
                        mma16816(acc[1][2 * t],     a[1], b0, b2);
                        mma16816(acc[1][2 * t + 1], a[1], b1, b3);
                    }
                }
            }
        }
    }

    // ---------------- epilogue: BN + ReLU -> bf16 pairs (+ fp16 for LAYER 1) ---
    u32* __restrict__ OUTP = (LAYER == 1) ? d_h1b2 : d_h2b2;
#pragma unroll
    for (int mt = 0; mt < 2; mt++) {
#pragma unroll
        for (int nt = 0; nt < 8; nt++) {
            int col = wn * 64 + nt * 8 + (lane & 3) * 2;
            float sc0 = s_sc[col], sc1 = s_sc[col + 1];
            float sh0 = s_sh[col], sh1 = s_sh[col + 1];
            int row = rbase + wm * 32 + mt * 16 + (lane >> 2);
            float v0 = fmaxf(fmaf(acc[mt][nt][0], sc0, sh0), 0.f);
            float v1 = fmaxf(fmaf(acc[mt][nt][1], sc1, sh1), 0.f);
            float v2 = fmaxf(fmaf(acc[mt][nt][2], sc0, sh0), 0.f);
            float v3 = fmaxf(fmaf(acc[mt][nt][3], sc1, sh1), 0.f);
            if (row < N_NODES) {
                *(uint2*)(OUTP + (size_t)row * HIDC + col) =
                    make_uint2(packb2(v0), packb2(v1));
                if (LAYER == 1)
                    d_h1h[(size_t)row * 64 + (col >> 1)] = h2u(__floats2half2_rn(v0, v1));
            }
            if (row + 8 < N_NODES) {
                *(uint2*)(OUTP + (size_t)(row + 8) * HIDC + col) =
                    make_uint2(packb2(v2), packb2(v3));
                if (LAYER == 1)
                    d_h1h[(size_t)(row + 8) * 64 + (col >> 1)] = h2u(__floats2half2_rn(v2, v3));
            }
        }
    }
}

// ---------------- layer-3 GEMM (mma.sync, 3-split) ----------------------------
// CTA tile 128 x 96 (cols 80..95 zero-pad), 8 warps 4(m)x2(n), 48 cols/warp.
// Epilogue: self cols -> d_zs fp32 (+bias); neigh cols -> d_z40h fp16.
__global__ __launch_bounds__(256, 2) void gemm80_mma(const float* __restrict__ b3) {
    __shared__ __align__(16) u16 sAhi[128 * APITCH];
    __shared__ __align__(16) u16 sAlo[128 * APITCH];
    __shared__ __align__(16) u16 sBhi[96 * APITCH];
    __shared__ __align__(16) u16 sBlo[96 * APITCH];
    __shared__ float s_b3[40];

    int tid = threadIdx.x, lane = tid & 31, wid = tid >> 5;
    int wm = wid >> 1, wn = wid & 1;
    int rbase = blockIdx.x * 128;

    if (tid < 40) s_b3[tid] = b3[tid];

    float acc[2][6][4];
#pragma unroll
    for (int mt = 0; mt < 2; mt++)
#pragma unroll
        for (int nt = 0; nt < 6; nt++)
#pragma unroll
            for (int r = 0; r < 4; r++) acc[mt][nt][r] = 0.f;

    int laneRow = (lane & 7) + ((lane >> 3) & 1) * 8;
    int laneK8  = (lane >> 4) * 8;
    u32 baseAhi = smem_u32(sAhi), baseAlo = smem_u32(sAlo);
    u32 baseBhi = smem_u32(sBhi), baseBlo = smem_u32(sBlo);

    for (int ck = 0; ck < 4; ++ck) {
        __syncthreads();
        // ---- B via cp.async first ----
#pragma unroll
        for (int i = 0; i < 3; i++) {
            int idx = tid + i * 256;        // 0..767
            int split = idx / 384, r = idx % 384;
            int row = r >> 2, q = r & 3;
            const void* g = d_wimg3 + ((size_t)(split * 4 + ck) * 96 + row) * 32 + q * 8;
            u16* dstb = split ? sBlo : sBhi;
            cp16(smem_u32(dstb + row * APITCH + q * 8), g);
        }
        // ---- A chunk: d_h2b2 pairs, 128 rows x 32 k ----
#pragma unroll
        for (int i = 0; i < 4; i++) {
            int idx = tid + i * 256;
            int row = idx >> 3, q = idx & 7;
            int grow = rbase + row; if (grow >= N_NODES) grow = N_NODES - 1;
            uint4 v = *(const uint4*)((const u32*)d_h2b2 + (size_t)grow * HIDC + ck * 32 + q * 4);
            u32* dh = (u32*)sAhi + row * (APITCH / 2) + q * 2;
            u32* dl = (u32*)sAlo + row * (APITCH / 2) + q * 2;
            dh[0] = __byte_perm(v.x, v.y, 0x5410);
            dh[1] = __byte_perm(v.z, v.w, 0x5410);
            dl[0] = __byte_perm(v.x, v.y, 0x7632);
            dl[1] = __byte_perm(v.z, v.w, 0x7632);
        }
        cp_commit_wait0();
        __syncthreads();
#pragma unroll
        for (int round = 0; round < 3; ++round) {
            u32 baseA = (round == 2) ? baseAlo : baseAhi;
            u32 baseB = (round == 1) ? baseBlo : baseBhi;
#pragma unroll
            for (int ks = 0; ks < 2; ++ks) {
                u32 a[2][4];
#pragma unroll
                for (int mt = 0; mt < 2; mt++) {
                    int arow = wm * 32 + mt * 16 + laneRow;
                    u32 addr = baseA + (u32)((arow * APITCH + ks * 16 + laneK8) * 2);
                    ldmx4(a[mt][0], a[mt][1], a[mt][2], a[mt][3], addr);
                }
#pragma unroll
                for (int t = 0; t < 3; t++) {
                    int brow = wn * 48 + t * 16 + laneRow;
                    u32 addr = baseB + (u32)((brow * APITCH + ks * 16 + laneK8) * 2);
                    u32 b0, b1, b2, b3v;
                    ldmx4(b0, b1, b2, b3v, addr);
                    mma16816(acc[0][2 * t],     a[0], b0, b2);
                    mma16816(acc[0][2 * t + 1], a[0], b1, b3v);
                    mma16816(acc[1][2 * t],     a[1], b0, b2);
                    mma16816(acc[1][2 * t + 1], a[1], b1, b3v);
                }
            }
        }
    }

    // ---------------- epilogue ----------------
#pragma unroll
    for (int mt = 0; mt < 2; mt++) {
#pragma unroll
        for (int nt = 0; nt < 6; nt++) {
            int col = wn * 48 + nt * 8 + (lane & 3) * 2;
            int row = rbase + wm * 32 + mt * 16 + (lane >> 2);
            if (col < 40) {
                float b0 = s_b3[col], b1 = s_b3[col + 1];
                if (row < N_NODES)
                    *(float2*)(d_zs + (size_t)row * 40 + col) =
                        make_float2(acc[mt][nt][0] + b0, acc[mt][nt][1] + b1);
                if (row + 8 < N_NODES)
                    *(float2*)(d_zs + (size_t)(row + 8) * 40 + col) =
                        make_float2(acc[mt][nt][2] + b0, acc[mt][nt][3] + b1);
            } else if (col < 80) {
                int c = (col - 40) >> 1;
                if (row < N_NODES)
                    d_z40h[(size_t)row * 20 + c] =
                        h2u(__floats2half2_rn(acc[mt][nt][0], acc[mt][nt][1]));
                if (row + 8 < N_NODES)
                    d_z40h[(size_t)(row + 8) * 20 + c] =
                        h2u(__floats2half2_rn(acc[mt][nt][2], acc[mt][nt][3]));
            }
        }
    }
}

// ------------- layer-3 aggregation (40 ch, fp16 gather) + log_softmax ---------
__global__ void agg40_lsm(float* __restrict__ out) {
    int w = (blockIdx.x * blockDim.x + threadIdx.x) >> 5;
    if (w >= N_NODES) return;
    int lane = threadIdx.x & 31;
    bool act = lane < 20;                 // lane owns channels 2*lane, 2*lane+1
    int s = d_rowptr[w], e = d_rowptr[w + 1];
    float acc0 = 0.f, acc1 = 0.f;
    int i = s;
    for (; i + 1 < e; i += 2) {
        int s0 = d_csr[i], s1 = d_csr[i + 1];
        if (act) {
            u32 v0 = __ldg(d_z40h + (size_t)s0 * 20 + lane);
            u32 v1 = __ldg(d_z40h + (size_t)s1 * 20 + lane);
            float2 f0 = u2f(v0), f1 = u2f(v1);
            acc0 += f0.x + f1.x; acc1 += f0.y + f1.y;
        }
    }
    if (i < e && act) {
        u32 v0 = __ldg(d_z40h + (size_t)d_csr[i] * 20 + lane);
        float2 f0 = u2f(v0);
        acc0 += f0.x; acc1 += f0.y;
    }
    float inv = (e > s) ? 1.0f / (float)(e - s) : 0.0f;
    float v0 = -1e30f, v1 = -1e30f;
    if (act) {
        float2 zs = *(const float2*)(d_zs + (size_t)w * 40 + lane * 2);
        v0 = zs.x + acc0 * inv;
        v1 = zs.y + acc1 * inv;
    }
    float m = fmaxf(v0, v1);
#pragma unroll
    for (int off = 16; off > 0; off >>= 1)
        m = fmaxf(m, __shfl_xor_sync(0xffffffffu, m, off));
    float se = act ? (expf(v0 - m) + expf(v1 - m)) : 0.f;
#pragma unroll
    for (int off = 16; off > 0; off >>= 1)
        se += __shfl_xor_sync(0xffffffffu, se, off);
    float lse = m + logf(se);
    if (act) {
        *(float2*)(out + (size_t)w * 40 + lane * 2) = make_float2(v0 - lse, v1 - lse);
    }
}

// ---------------- launch (pure kernel launches) ----------------
extern "C" void kernel_launch(void* const* d_in, const int* in_sizes, int n_in,
                              void* d_out, int out_size) {
    const float* x   = (const float*)d_in[0];
    const int*   ei  = (const int*)d_in[1];
    const float* Ws1 = (const float*)d_in[2];
    const float* Wn1 = (const float*)d_in[3];
    const float* b1  = (const float*)d_in[4];
    const float* Ws2 = (const float*)d_in[5];
    const float* Wn2 = (const float*)d_in[6];
    const float* b2  = (const float*)d_in[7];
    const float* Ws3 = (const float*)d_in[8];
    const float* Wn3 = (const float*)d_in[9];
    const float* b3  = (const float*)d_in[10];
    const float* g1  = (const float*)d_in[11];
    const float* be1 = (const float*)d_in[12];
    const float* m1  = (const float*)d_in[13];
    const float* v1  = (const float*)d_in[14];
    const float* g2  = (const float*)d_in[15];
    const float* be2 = (const float*)d_in[16];
    const float* m2  = (const float*)d_in[17];
    const float* v2  = (const float*)d_in[18];
    float* out = (float*)d_out;

    const int* src = ei;
    const int* dst = ei + N_EDGES;

    // merged prep: conv + zero_counts + weight images + BN constants (1 launch)
    prep_all<<<PREP_BLOCKS, 256>>>(x, Ws1, Wn1, Ws2, Wn2, Ws3, Wn3,
                                   b1, g1, be1, m1, v1, b2, g2, be2, m2, v2);

    // CSR build
    hist_kernel<<<(N_EDGES + 255) / 256, 256>>>(dst);
    scanA<<<SCAN_NB, 1024>>>();
    scanB<<<1, 32>>>();
    scanC<<<SCAN_NB, 1024>>>();
    fill_csr<<<(N_EDGES + 255) / 256, 256>>>(src, dst);

    const int gemm_blocks = (N_NODES + 127) / 128;     // 782
    const int agg_blocks  = (N_NODES + 7) / 8;

    // Layer 1
    agg128<0><<<agg_blocks, 256>>>();
    gemm_mma<1><<<gemm_blocks, 256>>>(x);
    // Layer 2
    agg128<1><<<agg_blocks, 256>>>();
    gemm_mma<2><<<gemm_blocks, 256>>>(nullptr);
    // Layer 3
    gemm80_mma<<<gemm_blocks, 256>>>(b3);
    agg40_lsm<<<agg_blocks, 256>>>(out);
}